// round 2
// baseline (speedup 1.0000x reference)
#include <cuda_runtime.h>
#include <math.h>

#define H  1024
#define V  50257
#define S  4096
#define G3 3072   // 3*H

// ---------------- scratch (no allocations allowed) ----------------
__device__ __align__(16) float g_rnn_in[2 * H];
__device__ __align__(16) float g_gi0[G3];
__device__ __align__(16) float g_gh0[G3];
__device__ __align__(16) float g_gi1[G3];
__device__ __align__(16) float g_gh1[G3];
__device__ __align__(16) float g_h0[H];
__device__ __align__(16) float g_h1[H];
__device__ __align__(16) float g_v[H];        // W_attn^T @ h1
__device__ __align__(16) float g_energ[S];
__device__ __align__(16) float g_attn[S];
__device__ __align__(16) float g_ctx[H];
__device__ __align__(16) float g_xcat[2 * H]; // [h1; context]
__device__ __align__(16) float g_logits[V + 16];
__device__ float g_ls[2];                     // {max, log(sum exp)}

// ---------------- helpers ----------------
__device__ __forceinline__ float warp_dot4(const float4* __restrict__ w,
                                           const float4* __restrict__ x,
                                           int n4, int lane) {
    float s = 0.f;
    for (int i = lane; i < n4; i += 32) {
        float4 a = w[i];
        float4 b = x[i];
        s = fmaf(a.x, b.x, s);
        s = fmaf(a.y, b.y, s);
        s = fmaf(a.z, b.z, s);
        s = fmaf(a.w, b.w, s);
    }
#pragma unroll
    for (int o = 16; o; o >>= 1) s += __shfl_down_sync(0xffffffffu, s, o);
    return s;
}

__device__ __forceinline__ float sigmoidf_(float x) {
    return 1.f / (1.f + __expf(-x));
}

// ---------------- K0: rnn_in = [emb[word], last_context] ----------------
__global__ void k_rnn_in(const int* __restrict__ word,
                         const float* __restrict__ emb,
                         const float* __restrict__ last_ctx) {
    int j = blockIdx.x * blockDim.x + threadIdx.x;
    if (j < H)            g_rnn_in[j] = emb[(size_t)word[0] * H + j];
    else if (j < 2 * H)   g_rnn_in[j] = last_ctx[j - H];
}

// ---------------- K1: gi0, gh0, gh1 GEMVs (all independent of h0/h1) ----
__global__ void k_gemv_pre(const float* __restrict__ Wih0,
                           const float* __restrict__ Whh0,
                           const float* __restrict__ Whh1,
                           const float* __restrict__ bih0,
                           const float* __restrict__ bhh0,
                           const float* __restrict__ bhh1,
                           const float* __restrict__ lh /* (2,1,H) */) {
    int warp = (blockIdx.x * blockDim.x + threadIdx.x) >> 5;
    int lane = threadIdx.x & 31;
    if (warp < G3) {
        float s = warp_dot4((const float4*)(Wih0 + (size_t)warp * 2048),
                            (const float4*)g_rnn_in, 512, lane);
        if (!lane) g_gi0[warp] = s + bih0[warp];
    } else if (warp < 2 * G3) {
        int r = warp - G3;
        float s = warp_dot4((const float4*)(Whh0 + (size_t)r * H),
                            (const float4*)lh, 256, lane);
        if (!lane) g_gh0[r] = s + bhh0[r];
    } else if (warp < 3 * G3) {
        int r = warp - 2 * G3;
        float s = warp_dot4((const float4*)(Whh1 + (size_t)r * H),
                            (const float4*)(lh + H), 256, lane);
        if (!lane) g_gh1[r] = s + bhh1[r];
    }
}

// ---------------- K2: GRU0 gates -> h0 (also hidden[0] output) ----------
__global__ void k_gate0(const float* __restrict__ lh, float* __restrict__ out) {
    int t = threadIdx.x; // blockDim = 1024
    float r = sigmoidf_(g_gi0[t] + g_gh0[t]);
    float z = sigmoidf_(g_gi0[H + t] + g_gh0[H + t]);
    float n = tanhf(g_gi0[2 * H + t] + r * g_gh0[2 * H + t]);
    float h = (1.f - z) * n + z * lh[t];
    g_h0[t] = h;
    out[V + H + t] = h;   // hidden[0]
}

// ---------------- K3: gi1 = W_ih1 @ h0 ----------------
__global__ void k_gemv_gi1(const float* __restrict__ Wih1,
                           const float* __restrict__ bih1) {
    int warp = (blockIdx.x * blockDim.x + threadIdx.x) >> 5;
    int lane = threadIdx.x & 31;
    if (warp < G3) {
        float s = warp_dot4((const float4*)(Wih1 + (size_t)warp * H),
                            (const float4*)g_h0, 256, lane);
        if (!lane) g_gi1[warp] = s + bih1[warp];
    }
}

// ---------------- K4: GRU1 gates -> h1 (also hidden[1]); zero g_v -------
__global__ void k_gate1(const float* __restrict__ lh, float* __restrict__ out) {
    int t = threadIdx.x;
    float r = sigmoidf_(g_gi1[t] + g_gh1[t]);
    float z = sigmoidf_(g_gi1[H + t] + g_gh1[H + t]);
    float n = tanhf(g_gi1[2 * H + t] + r * g_gh1[2 * H + t]);
    float h = (1.f - z) * n + z * lh[H + t];
    g_h1[t] = h;
    out[V + 2 * H + t] = h;  // hidden[1]
    g_v[t] = 0.f;
}

// ---------------- K5: v = W_attn^T @ h1 (column reduction) --------------
// grid = (H/256 col-chunks, row-chunks), block = 256
__global__ void k_attn_v(const float* __restrict__ Wattn) {
    int j  = blockIdx.x * 256 + threadIdx.x;
    int i0 = blockIdx.y * 128;
    float s = 0.f;
#pragma unroll 4
    for (int i = i0; i < i0 + 128; i++)
        s = fmaf(Wattn[(size_t)i * H + j], g_h1[i], s);
    atomicAdd(&g_v[j], s);
}

// ---------------- K6: energies[s] = enc[s] . v --------------------------
__global__ void k_energ(const float* __restrict__ enc) {
    int warp = (blockIdx.x * blockDim.x + threadIdx.x) >> 5;
    int lane = threadIdx.x & 31;
    if (warp < S) {
        float s = warp_dot4((const float4*)(enc + (size_t)warp * H),
                            (const float4*)g_v, 256, lane);
        if (!lane) g_energ[warp] = s;
    }
}

// ---------------- K7: softmax over energies; write attn_weights; zero ctx
__global__ void k_softmax(float* __restrict__ out) {
    __shared__ float shm[32];
    __shared__ float shs[32];
    __shared__ float bmax, bsum;
    int t = threadIdx.x, lane = t & 31, w = t >> 5;

    float m = -INFINITY;
    for (int i = t; i < S; i += 1024) m = fmaxf(m, g_energ[i]);
#pragma unroll
    for (int o = 16; o; o >>= 1) m = fmaxf(m, __shfl_down_sync(0xffffffffu, m, o));
    if (!lane) shm[w] = m;
    __syncthreads();
    if (w == 0) {
        m = shm[lane];
#pragma unroll
        for (int o = 16; o; o >>= 1) m = fmaxf(m, __shfl_down_sync(0xffffffffu, m, o));
        if (!lane) bmax = m;
    }
    __syncthreads();

    float sum = 0.f;
    for (int i = t; i < S; i += 1024) sum += __expf(g_energ[i] - bmax);
#pragma unroll
    for (int o = 16; o; o >>= 1) sum += __shfl_down_sync(0xffffffffu, sum, o);
    if (!lane) shs[w] = sum;
    __syncthreads();
    if (w == 0) {
        sum = shs[lane];
#pragma unroll
        for (int o = 16; o; o >>= 1) sum += __shfl_down_sync(0xffffffffu, sum, o);
        if (!lane) bsum = sum;
    }
    __syncthreads();

    float inv = 1.f / bsum;
    for (int i = t; i < S; i += 1024) {
        float a = __expf(g_energ[i] - bmax) * inv;
        g_attn[i] = a;
        out[V + 3 * H + i] = a;  // attn_weights
    }
    g_ctx[t] = 0.f;  // blockDim == H
}

// ---------------- K8: context = attn @ enc ------------------------------
// grid = (4 col-chunks, 16 row-chunks), block 256
__global__ void k_ctx(const float* __restrict__ enc) {
    int j  = blockIdx.x * 256 + threadIdx.x;
    int s0 = blockIdx.y * 256;
    float acc = 0.f;
#pragma unroll 4
    for (int s = s0; s < s0 + 256; s++)
        acc = fmaf(g_attn[s], enc[(size_t)s * H + j], acc);
    atomicAdd(&g_ctx[j], acc);
}

// ---------------- K8b: xcat = [h1; ctx]; write context output -----------
__global__ void k_xcat(float* __restrict__ out) {
    int j = blockIdx.x * 1024 + threadIdx.x;  // grid = 2
    if (j < H) {
        g_xcat[j] = g_h1[j];
    } else {
        float c = g_ctx[j - H];
        g_xcat[j] = c;
        out[V + (j - H)] = c;  // context
    }
}

// ---------------- K9: logits = W_out @ xcat + b_out (412MB, HBM-bound) --
__global__ void k_logits(const float* __restrict__ Wout,
                         const float* __restrict__ bout) {
    int warp = (blockIdx.x * blockDim.x + threadIdx.x) >> 5;
    int lane = threadIdx.x & 31;
    if (warp < V) {
        float s = warp_dot4((const float4*)(Wout + (size_t)warp * 2048),
                            (const float4*)g_xcat, 512, lane);
        if (!lane) g_logits[warp] = s + bout[warp];
    }
}

// ---------------- K10: logsumexp over logits ----------------------------
__global__ void k_lse() {
    __shared__ float shm[32];
    __shared__ float shs[32];
    __shared__ float bmax;
    int t = threadIdx.x, lane = t & 31, w = t >> 5;

    float m = -INFINITY;
    for (int i = t; i < V; i += 1024) m = fmaxf(m, g_logits[i]);
#pragma unroll
    for (int o = 16; o; o >>= 1) m = fmaxf(m, __shfl_down_sync(0xffffffffu, m, o));
    if (!lane) shm[w] = m;
    __syncthreads();
    if (w == 0) {
        m = shm[lane];
#pragma unroll
        for (int o = 16; o; o >>= 1) m = fmaxf(m, __shfl_down_sync(0xffffffffu, m, o));
        if (!lane) bmax = m;
    }
    __syncthreads();

    float sum = 0.f;
    for (int i = t; i < V; i += 1024) sum += __expf(g_logits[i] - bmax);
#pragma unroll
    for (int o = 16; o; o >>= 1) sum += __shfl_down_sync(0xffffffffu, sum, o);
    if (!lane) shs[w] = sum;
    __syncthreads();
    if (w == 0) {
        sum = shs[lane];
#pragma unroll
        for (int o = 16; o; o >>= 1) sum += __shfl_down_sync(0xffffffffu, sum, o);
        if (!lane) {
            g_ls[0] = bmax;
            g_ls[1] = logf(sum);
        }
    }
}

// ---------------- K11: output = logits - max - log(sum) -----------------
__global__ void k_out(float* __restrict__ out) {
    int i = blockIdx.x * blockDim.x + threadIdx.x;
    if (i < V) out[i] = g_logits[i] - g_ls[0] - g_ls[1];
}

// ---------------- launch ----------------
extern "C" void kernel_launch(void* const* d_in, const int* in_sizes, int n_in,
                              void* d_out, int out_size) {
    const int*   word  = (const int*)  d_in[0];
    const float* lctx  = (const float*)d_in[1];
    const float* lh    = (const float*)d_in[2];   // (2,1,H)
    const float* enc   = (const float*)d_in[3];   // (S,1,H)
    const float* emb   = (const float*)d_in[4];   // (V,H)
    const float* Wih0  = (const float*)d_in[5];   // (3H,2H)
    const float* Whh0  = (const float*)d_in[6];   // (3H,H)
    const float* bih0  = (const float*)d_in[7];
    const float* bhh0  = (const float*)d_in[8];
    const float* Wih1  = (const float*)d_in[9];   // (3H,H)
    const float* Whh1  = (const float*)d_in[10];  // (3H,H)
    const float* bih1  = (const float*)d_in[11];
    const float* bhh1  = (const float*)d_in[12];
    // d_in[13] = W_attn, d_in[14] = b_attn (b_attn provably cancels in softmax)
    const float* Wattn = (const float*)d_in[13];
    const float* Wout  = (const float*)d_in[15];  // (V,2H)
    const float* bout  = (const float*)d_in[16];
    float* out = (float*)d_out;

    k_rnn_in<<<8, 256>>>(word, emb, lctx);
    // 3*G3 = 9216 warps -> 9216*32/256 = 1152 blocks
    k_gemv_pre<<<1152, 256>>>(Wih0, Whh0, Whh1, bih0, bhh0, bhh1, lh);
    k_gate0<<<1, 1024>>>(lh, out);
    k_gemv_gi1<<<384, 256>>>(Wih1, bih1);
    k_gate1<<<1, 1024>>>(lh, out);
    k_attn_v<<<dim3(4, 8), 256>>>(Wattn);
    k_energ<<<512, 256>>>(enc);
    k_softmax<<<1, 1024>>>(out);
    k_ctx<<<dim3(4, 16), 256>>>(enc);
    k_xcat<<<2, 1024>>>(out);
    k_logits<<<(V + 7) / 8, 256>>>(Wout, bout);   // warp per row, 8 warps/block
    k_lse<<<1, 1024>>>();
    k_out<<<(V + 255) / 256, 256>>>(out);
}

// round 7
// speedup vs baseline: 1.3032x; 1.3032x over previous
#include <cuda_runtime.h>
#include <math.h>

#define H   1024
#define V   50257
#define S   4096
#define G3  3072            // 3*H
#define NB  148             // blocks (<= SM count, 1 block/SM resident)
#define NT  1024
#define NWARP (NB * 32)     // 4736 warps total
#define ROWS_PB 340         // ceil(V / NB)
#define SCH 28              // ceil(S / NB)
#define ICH 7               // ceil(H / NB)

// ---------------- global scratch (no allocations allowed) ----------------
__device__ float g_gi0[G3];
__device__ float g_gh0[G3];
__device__ float g_gi1[G3];
__device__ float g_gh1[G3];
__device__ float g_v[H];
__device__ float g_energ[S];
__device__ float g_ctx[H];
__device__ float g_part[2 * NB];          // per-block (max, sumexp)
__device__ unsigned g_count;              // barrier arrival counter
__device__ volatile unsigned g_epoch;     // barrier epoch (monotonic across replays)

// ---------------- software grid barrier (all 148 blocks resident) --------
__device__ __forceinline__ void gsync() {
    __syncthreads();
    if (threadIdx.x == 0) {
        __threadfence();
        unsigned e = g_epoch;
        if (atomicAdd(&g_count, 1) == (unsigned)(gridDim.x - 1)) {
            g_count = 0;
            __threadfence();
            g_epoch = e + 1;                 // release
        } else {
            while (g_epoch == e) __nanosleep(32);
        }
        __threadfence();
    }
    __syncthreads();
}

__device__ __forceinline__ float sigmoidf_(float x) {
    return 1.f / (1.f + __expf(-x));
}

// warp dot: w global, x shared; n4 in {256, 512} (multiple of 128)
__device__ __forceinline__ float wdot(const float4* __restrict__ w,
                                      const float4* __restrict__ x,
                                      int n4, int lane) {
    float s0 = 0.f, s1 = 0.f, s2 = 0.f, s3 = 0.f;
#pragma unroll 4
    for (int i = lane; i < n4; i += 128) {
        float4 a0 = w[i];        float4 b0 = x[i];
        float4 a1 = w[i + 32];   float4 b1 = x[i + 32];
        float4 a2 = w[i + 64];   float4 b2 = x[i + 64];
        float4 a3 = w[i + 96];   float4 b3 = x[i + 96];
        s0 = fmaf(a0.x, b0.x, fmaf(a0.y, b0.y, fmaf(a0.z, b0.z, fmaf(a0.w, b0.w, s0))));
        s1 = fmaf(a1.x, b1.x, fmaf(a1.y, b1.y, fmaf(a1.z, b1.z, fmaf(a1.w, b1.w, s1))));
        s2 = fmaf(a2.x, b2.x, fmaf(a2.y, b2.y, fmaf(a2.z, b2.z, fmaf(a2.w, b2.w, s2))));
        s3 = fmaf(a3.x, b3.x, fmaf(a3.y, b3.y, fmaf(a3.z, b3.z, fmaf(a3.w, b3.w, s3))));
    }
    float s = (s0 + s1) + (s2 + s3);
#pragma unroll
    for (int o = 16; o; o >>= 1) s += __shfl_xor_sync(0xffffffffu, s, o);
    return s;
}

__global__ void __launch_bounds__(NT, 1)
decoder_kernel(const int* __restrict__ word, const float* __restrict__ lctx,
               const float* __restrict__ lh, const float* __restrict__ enc,
               const float* __restrict__ emb,
               const float* __restrict__ Wih0, const float* __restrict__ Whh0,
               const float* __restrict__ bih0, const float* __restrict__ bhh0,
               const float* __restrict__ Wih1, const float* __restrict__ Whh1,
               const float* __restrict__ bih1, const float* __restrict__ bhh1,
               const float* __restrict__ Wattn, const float* __restrict__ Wout,
               const float* __restrict__ bout, float* __restrict__ out) {
    __shared__ float sh_in[2 * H];       // [emb_row ; last_context]
    __shared__ float sh_lh[2 * H];       // last_hidden[0], last_hidden[1]
    __shared__ float sh_h0[H];           // h0 (later reused to stage v)
    __shared__ float sh_xcat[2 * H];     // [h1 ; context]
    __shared__ float sh_logit[ROWS_PB];  // this block's logits chunk
    __shared__ float sh_a[SCH];          // this block's attn chunk
    __shared__ float sh_red[32];
    __shared__ float sh_bc[2];

    const int t = threadIdx.x;
    const int lane = t & 31;
    const int wid = t >> 5;
    const int b = blockIdx.x;
    const int gw = b * 32 + wid;

    // stage inputs into shared
    {
        int w0 = word[0];
        sh_in[t]     = emb[(size_t)w0 * H + t];
        sh_in[H + t] = lctx[t];
        sh_lh[t]     = lh[t];
        sh_lh[H + t] = lh[H + t];
    }
    if (b == 0) { g_v[t] = 0.f; g_ctx[t] = 0.f; }
    __syncthreads();

    // ---------- phase 1: gi0 (3072 rows, dot 2048) + gh0 + gh1 (dot 1024) ----
    for (int r = gw; r < 3 * G3; r += NWARP) {
        if (r < G3) {
            float s = wdot((const float4*)(Wih0 + (size_t)r * 2 * H),
                           (const float4*)sh_in, 512, lane);
            if (!lane) g_gi0[r] = s + bih0[r];
        } else if (r < 2 * G3) {
            int rr = r - G3;
            float s = wdot((const float4*)(Whh0 + (size_t)rr * H),
                           (const float4*)sh_lh, 256, lane);
            if (!lane) g_gh0[rr] = s + bhh0[rr];
        } else {
            int rr = r - 2 * G3;
            float s = wdot((const float4*)(Whh1 + (size_t)rr * H),
                           (const float4*)(sh_lh + H), 256, lane);
            if (!lane) g_gh1[rr] = s + bhh1[rr];
        }
    }
    gsync();

    // ---------- phase 2: per-block h0 recompute; gi1 = W_ih1 @ h0 ------------
    {
        float r_ = sigmoidf_(g_gi0[t] + g_gh0[t]);
        float z  = sigmoidf_(g_gi0[H + t] + g_gh0[H + t]);
        float n  = tanhf(g_gi0[2 * H + t] + r_ * g_gh0[2 * H + t]);
        float h  = (1.f - z) * n + z * sh_lh[t];
        sh_h0[t] = h;
        if (b == 0) out[V + H + t] = h;   // hidden[0]
    }
    __syncthreads();
    if (gw < G3) {
        float s = wdot((const float4*)(Wih1 + (size_t)gw * H),
                       (const float4*)sh_h0, 256, lane);
        if (!lane) g_gi1[gw] = s + bih1[gw];
    }
    gsync();

    // ---------- phase 3: per-block h1 recompute; v partials (W_attn^T h1) ----
    {
        float r_ = sigmoidf_(g_gi1[t] + g_gh1[t]);
        float z  = sigmoidf_(g_gi1[H + t] + g_gh1[H + t]);
        float n  = tanhf(g_gi1[2 * H + t] + r_ * g_gh1[2 * H + t]);
        float h  = (1.f - z) * n + z * sh_lh[H + t];
        sh_xcat[t] = h;                    // xcat[0:H] = h1 (persists to phase 7)
        if (b == 0) out[V + 2 * H + t] = h; // hidden[1]
    }
    __syncthreads();
    {
        float acc = 0.f;
        int i0 = b * ICH;
#pragma unroll
        for (int k = 0; k < ICH; k++) {
            int i = i0 + k;
            if (i < H) acc = fmaf(Wattn[(size_t)i * H + t], sh_xcat[i], acc);
        }
        atomicAdd(&g_v[t], acc);
    }
    gsync();

    // ---------- phase 4: energies[s] = enc[s] . v ---------------------------
    sh_h0[t] = g_v[t];                    // reuse sh_h0 to stage v
    __syncthreads();
    if (gw < S) {
        float s = wdot((const float4*)(enc + (size_t)gw * H),
                       (const float4*)sh_h0, 256, lane);
        if (!lane) g_energ[gw] = s;
    }
    gsync();

    // ---------- phase 5: softmax (redundant per block) + ctx partials -------
    {
        float m = -INFINITY;
        for (int i = t; i < S; i += NT) m = fmaxf(m, g_energ[i]);
#pragma unroll
        for (int o = 16; o; o >>= 1) m = fmaxf(m, __shfl_xor_sync(0xffffffffu, m, o));
        if (!lane) sh_red[wid] = m;
        __syncthreads();
        if (wid == 0) {
            m = sh_red[lane];
#pragma unroll
            for (int o = 16; o; o >>= 1) m = fmaxf(m, __shfl_xor_sync(0xffffffffu, m, o));
            if (!lane) sh_bc[0] = m;
        }
        __syncthreads();
        float bmax = sh_bc[0];
        float sum = 0.f;
        for (int i = t; i < S; i += NT) sum += __expf(g_energ[i] - bmax);
#pragma unroll
        for (int o = 16; o; o >>= 1) sum += __shfl_xor_sync(0xffffffffu, sum, o);
        if (!lane) sh_red[wid] = sum;
        __syncthreads();
        if (wid == 0) {
            sum = sh_red[lane];
#pragma unroll
            for (int o = 16; o; o >>= 1) sum += __shfl_xor_sync(0xffffffffu, sum, o);
            if (!lane) sh_bc[1] = sum;
        }
        __syncthreads();
        float inv = 1.f / sh_bc[1];
        int s0 = b * SCH;
        if (t < SCH && s0 + t < S) {
            float a = __expf(g_energ[s0 + t] - bmax) * inv;
            sh_a[t] = a;
            out[V + 3 * H + s0 + t] = a;  // attn_weights
        }
        __syncthreads();
        float acc = 0.f;
#pragma unroll
        for (int k = 0; k < SCH; k++) {
            int s = s0 + k;
            if (s < S) acc = fmaf(sh_a[k], enc[(size_t)s * H + t], acc);
        }
        atomicAdd(&g_ctx[t], acc);
    }
    gsync();

    // ---------- phase 6: logits chunk (dominant 412 MB) + block LSE ---------
    sh_xcat[H + t] = g_ctx[t];
    if (b == 0) out[V + t] = g_ctx[t];    // context
    __syncthreads();
    const int base = b * ROWS_PB;
    const int nrows = min(ROWS_PB, V - base);
    for (int rl = wid; rl < nrows; rl += 32) {
        int r = base + rl;
        float s = wdot((const float4*)(Wout + (size_t)r * 2 * H),
                       (const float4*)sh_xcat, 512, lane);
        if (!lane) sh_logit[rl] = s + bout[r];
    }
    __syncthreads();
    {
        float m = -INFINITY;
        for (int i = t; i < nrows; i += NT) m = fmaxf(m, sh_logit[i]);
#pragma unroll
        for (int o = 16; o; o >>= 1) m = fmaxf(m, __shfl_xor_sync(0xffffffffu, m, o));
        if (!lane) sh_red[wid] = m;
        __syncthreads();
        if (wid == 0) {
            m = sh_red[lane];
#pragma unroll
            for (int o = 16; o; o >>= 1) m = fmaxf(m, __shfl_xor_sync(0xffffffffu, m, o));
            if (!lane) sh_bc[0] = m;
        }
        __syncthreads();
        float bmax = sh_bc[0];
        float sum = 0.f;
        for (int i = t; i < nrows; i += NT) sum += __expf(sh_logit[i] - bmax);
#pragma unroll
        for (int o = 16; o; o >>= 1) sum += __shfl_xor_sync(0xffffffffu, sum, o);
        if (!lane) sh_red[wid] = sum;
        __syncthreads();
        if (wid == 0) {
            sum = sh_red[lane];
#pragma unroll
            for (int o = 16; o; o >>= 1) sum += __shfl_xor_sync(0xffffffffu, sum, o);
            if (!lane) { g_part[2 * b] = bmax; g_part[2 * b + 1] = sum; }
        }
    }
    gsync();

    // ---------- phase 7: merge 148 (max,sum) pairs; write log_softmax -------
    {
        if (wid == 0) {
            float m = -INFINITY, sacc = 0.f;
            for (int i = lane; i < NB; i += 32) {
                float mi = g_part[2 * i], si = g_part[2 * i + 1];
                float mn = fmaxf(m, mi);
                sacc = sacc * __expf(m - mn) + si * __expf(mi - mn);
                m = mn;
            }
#pragma unroll
            for (int o = 16; o; o >>= 1) {
                float mo = __shfl_xor_sync(0xffffffffu, m, o);
                float so = __shfl_xor_sync(0xffffffffu, sacc, o);
                float mn = fmaxf(m, mo);
                sacc = sacc * __expf(m - mn) + so * __expf(mo - mn);
                m = mn;
            }
            if (!lane) { sh_bc[0] = m; sh_bc[1] = logf(sacc); }
        }
        __syncthreads();
        float mm = sh_bc[0], ls = sh_bc[1];
        for (int i = t; i < nrows; i += NT)
            out[base + i] = sh_logit[i] - mm - ls;
    }
}

// ---------------- launch ----------------
extern "C" void kernel_launch(void* const* d_in, const int* in_sizes, int n_in,
                              void* d_out, int out_size) {
    const int*   word  = (const int*)  d_in[0];
    const float* lctx  = (const float*)d_in[1];
    const float* lh    = (const float*)d_in[2];
    const float* enc   = (const float*)d_in[3];
    const float* emb   = (const float*)d_in[4];
    const float* Wih0  = (const float*)d_in[5];
    const float* Whh0  = (const float*)d_in[6];
    const float* bih0  = (const float*)d_in[7];
    const float* bhh0  = (const float*)d_in[8];
    const float* Wih1  = (const float*)d_in[9];
    const float* Whh1  = (const float*)d_in[10];
    const float* bih1  = (const float*)d_in[11];
    const float* bhh1  = (const float*)d_in[12];
    const float* Wattn = (const float*)d_in[13];
    // d_in[14] = b_attn: cancels in softmax (constant shift per row)
    const float* Wout  = (const float*)d_in[15];
    const float* bout  = (const float*)d_in[16];
    float* out = (float*)d_out;

    decoder_kernel<<<NB, NT>>>(word, lctx, lh, enc, emb,
                               Wih0, Whh0, bih0, bhh0,
                               Wih1, Whh1, bih1, bhh1,
                               Wattn, Wout, bout, out);
}